// round 7
// baseline (speedup 1.0000x reference)
#include <cuda_runtime.h>
#include <cuda_fp16.h>
#include <cstdint>

#define NN 8192
#define FD 128
#define ALPHA 0.2f

__device__ float  g_es[NN], g_ed[NN], g_maxed;
__device__ float  g_A[NN], g_B[NN];
__device__ float4 g_jp[NN];                 // {ed, exp(ed), exp(.2 ed), 0}
__device__ __half g_WhT[(size_t)FD * NN];   // [f][node]

__device__ __forceinline__ float leakyf(float x) { return fmaxf(x, ALPHA * x); }
__device__ __forceinline__ uint32_t packh2(float x, float y) {
    __half2 h = __floats2half2_rn(x, y);
    return reinterpret_cast<uint32_t&>(h);
}
__device__ __forceinline__ void mma16816(float* c,
                                         uint32_t a0, uint32_t a1, uint32_t a2, uint32_t a3,
                                         uint32_t b0, uint32_t b1) {
    asm volatile(
        "mma.sync.aligned.m16n8k16.row.col.f32.f16.f16.f32 "
        "{%0,%1,%2,%3}, {%4,%5,%6,%7}, {%8,%9}, {%0,%1,%2,%3};\n"
        : "+f"(c[0]), "+f"(c[1]), "+f"(c[2]), "+f"(c[3])
        : "r"(a0), "r"(a1), "r"(a2), "r"(a3), "r"(b0), "r"(b1));
}
__device__ __forceinline__ void cp16(void* s, const void* g) {
    unsigned sa = (unsigned)__cvta_generic_to_shared(s);
    asm volatile("cp.async.cg.shared.global [%0], [%1], 16;\n" :: "r"(sa), "l"(g));
}
__device__ __forceinline__ void ldm4(uint32_t* r, uint32_t a) {
    asm volatile("ldmatrix.sync.aligned.m8n8.x4.shared.b16 {%0,%1,%2,%3}, [%4];"
                 : "=r"(r[0]), "=r"(r[1]), "=r"(r[2]), "=r"(r[3]) : "r"(a));
}

// ---------------- k_wh: Wh = h@W fp32, WhT fp16, es, ed (unchanged) ----------
__global__ void __launch_bounds__(256) k_wh(const float* __restrict__ h,
                                            const float* __restrict__ Wm,
                                            const float* __restrict__ a) {
    __shared__ __align__(16) char sbuf[64 * 132 * 4];
    __shared__ float sWa1[FD], sWa2[FD];
    float (*sW)[128]  = reinterpret_cast<float(*)[128]>(sbuf);
    float (*sH)[33]   = reinterpret_cast<float(*)[33]>(sbuf + 16384);
    float (*sWh)[132] = reinterpret_cast<float(*)[132]>(sbuf);
    const int t = threadIdx.x, tx = t & 31, ty = t >> 5;
    const int i0 = blockIdx.x * 64;
    if (t < FD) { sWa1[t] = a[t]; sWa2[t] = a[FD + t]; }
    float acc[8][4];
#pragma unroll
    for (int r = 0; r < 8; ++r)
#pragma unroll
        for (int c = 0; c < 4; ++c) acc[r][c] = 0.f;
    for (int kb = 0; kb < 4; ++kb) {
        const int k0 = kb * 32;
        __syncthreads();
#pragma unroll
        for (int m = 0; m < 16; ++m) {
            int idx = t + m * 256, r = idx >> 7, c = idx & 127;
            sW[r][c] = Wm[(k0 + r) * FD + c];
        }
#pragma unroll
        for (int m = 0; m < 8; ++m) {
            int idx = t + m * 256, r = idx >> 5, c = idx & 31;
            sH[r][c] = h[(size_t)(i0 + r) * FD + k0 + c];
        }
        __syncthreads();
#pragma unroll 4
        for (int kk = 0; kk < 32; ++kk) {
            float4 bv = *(const float4*)&sW[kk][tx * 4];
#pragma unroll
            for (int rr = 0; rr < 8; ++rr) {
                float av = sH[ty * 8 + rr][kk];
                acc[rr][0] += av * bv.x; acc[rr][1] += av * bv.y;
                acc[rr][2] += av * bv.z; acc[rr][3] += av * bv.w;
            }
        }
    }
    __syncthreads();
#pragma unroll
    for (int rr = 0; rr < 8; ++rr)
        *(float4*)&sWh[ty * 8 + rr][tx * 4] =
            make_float4(acc[rr][0], acc[rr][1], acc[rr][2], acc[rr][3]);
    __syncthreads();
#pragma unroll
    for (int rr = 0; rr < 8; ++rr) {
        int r = ty * 8 + rr;
        float4 v = *(const float4*)&sWh[r][tx * 4];
        float s1 = v.x*sWa1[tx*4] + v.y*sWa1[tx*4+1] + v.z*sWa1[tx*4+2] + v.w*sWa1[tx*4+3];
        float s2 = v.x*sWa2[tx*4] + v.y*sWa2[tx*4+1] + v.z*sWa2[tx*4+2] + v.w*sWa2[tx*4+3];
#pragma unroll
        for (int off = 16; off; off >>= 1) {
            s1 += __shfl_xor_sync(0xffffffffu, s1, off);
            s2 += __shfl_xor_sync(0xffffffffu, s2, off);
        }
        if (tx == 0) { g_es[i0 + r] = s1; g_ed[i0 + r] = s2; }
    }
    {
        int c = t >> 1, roff = (t & 1) * 32;
#pragma unroll 8
        for (int i = 0; i < 32; ++i)
            g_WhT[(size_t)c * NN + i0 + roff + i] = __float2half(sWh[roff + i][c]);
    }
}

__global__ void k_max() {
    __shared__ float red[256];
    int t = threadIdx.x;
    float m = -1e30f;
    for (int i = t; i < NN; i += 256) m = fmaxf(m, g_ed[i]);
    red[t] = m;
    __syncthreads();
#pragma unroll
    for (int s = 128; s; s >>= 1) {
        if (t < s) red[t] = fmaxf(red[t], red[t + s]);
        __syncthreads();
    }
    if (t == 0) g_maxed = red[0];
}
__global__ void k_pre() {
    int i = blockIdx.x * 512 + threadIdx.x;
    float mx = g_maxed;
    float es = g_es[i], ed = g_ed[i];
    float m = leakyf(es + mx);
    g_A[i] = __expf(es - m);
    g_B[i] = __expf(0.2f * es - m);
    g_jp[i] = make_float4(ed, __expf(ed), __expf(0.2f * ed), 0.f);
}

// ---------------- k_flash ----------------------------------------------------
// 128 CTAs x 64 rows x 512 thr. 16 warps = 4 row-groups(16) x 4 col-groups(32).
#define PITCH 272
#define OFF_P  0
#define OFF_W0 17408
#define OFF_W1 52224
#define OFF_J0 87040
#define OFF_J1 89216
#define OFF_LS 91392
#define SMEMSZ 91648

__global__ void __launch_bounds__(512, 1) k_flash(const int* __restrict__ adj,
                                                  float* __restrict__ out) {
    extern __shared__ __align__(16) char sm[];
    const uint32_t smu = (uint32_t)__cvta_generic_to_shared(sm);
    const int t = threadIdx.x, l = t & 31, w = t >> 5;
    const int rg = w >> 2, nc = w & 3;
    const int i0 = blockIdx.x * 64;
    const int prow = t >> 3;          // P row 0..63
    const int pg = t & 7;             // P col group (16 j each)
    const int pc = pg * 16;

    const float esm = g_es[i0 + prow];
    const float Am  = g_A[i0 + prow];
    const float Bm  = g_B[i0 + prow];
    const int* arow = adj + (size_t)(i0 + prow) * NN + pc;

    auto issue = [&](int buf, int jb) {
        const int j0 = jb * 128;
        char* Wt = sm + (buf ? OFF_W1 : OFF_W0);
        char* J  = sm + (buf ? OFF_J1 : OFF_J0);
#pragma unroll
        for (int mm = 0; mm < 4; ++mm) {
            int idx = t + mm * 512;
            int f = idx >> 4, c8 = idx & 15;
            cp16(Wt + f * PITCH + c8 * 16, g_WhT + (size_t)f * NN + j0 + c8 * 8);
        }
        if (t < 128) cp16(J + (t + (t >> 4)) * 16, g_jp + j0 + t);  // padded layout
    };

    issue(0, 0);
    asm volatile("cp.async.commit_group;\n");

    int4 areg[4];
#pragma unroll
    for (int u = 0; u < 4; ++u) areg[u] = *(const int4*)(arow + u * 4);

    float acc[4][4];
#pragma unroll
    for (int n = 0; n < 4; ++n)
#pragma unroll
        for (int i = 0; i < 4; ++i) acc[n][i] = 0.f;
    float ls = 0.f;

    char* Pp = sm + OFF_P + prow * PITCH + pc * 2;
    const uint32_t Pb = smu + OFF_P + (rg * 16 + (l & 15)) * PITCH + (l >> 4) * 16;
    const uint32_t Wcol = (uint32_t)((nc * 32 + (l & 7)) * PITCH + (l >> 3) * 16);

    for (int jb = 0; jb < 64; ++jb) {
        const int buf = jb & 1;
        __syncthreads();                        // everyone done with buf^1 & P
        if (jb + 1 < 64) issue(buf ^ 1, jb + 1);
        asm volatile("cp.async.commit_group;\n");
        asm volatile("cp.async.wait_group 1;\n");
        __syncthreads();

        // ---- P phase: 16 elements/thread ----
        const float4* Jt = (const float4*)(sm + (buf ? OFF_J1 : OFF_J0)) + pc + pg;
#pragma unroll
        for (int u = 0; u < 4; ++u) {
            int4 q = areg[u];
            float4 j0v = Jt[u*4+0], j1v = Jt[u*4+1], j2v = Jt[u*4+2], j3v = Jt[u*4+3];
            float p0 = (esm + j0v.x >= 0.f) ? Am * j0v.y : Bm * j0v.z; p0 = q.x ? p0 : 0.f;
            float p1 = (esm + j1v.x >= 0.f) ? Am * j1v.y : Bm * j1v.z; p1 = q.y ? p1 : 0.f;
            float p2 = (esm + j2v.x >= 0.f) ? Am * j2v.y : Bm * j2v.z; p2 = q.z ? p2 : 0.f;
            float p3 = (esm + j3v.x >= 0.f) ? Am * j3v.y : Bm * j3v.z; p3 = q.w ? p3 : 0.f;
            ls += (p0 + p1) + (p2 + p3);
            uint2 pk; pk.x = packh2(p0, p1); pk.y = packh2(p2, p3);
            *(uint2*)(Pp + u * 8) = pk;
        }
        if (jb + 1 < 64) {                       // adj prefetch (hidden by mma phase)
            const int* an = arow + (jb + 1) * 128;
#pragma unroll
            for (int u = 0; u < 4; ++u) areg[u] = *(const int4*)(an + u * 4);
        }
        __syncthreads();

        // ---- MMA phase: warp (rg, nc), A 16x128 via ldmatrix, B 32 cols ----
        const uint32_t Wb = smu + (buf ? OFF_W1 : OFF_W0) + Wcol;
#pragma unroll
        for (int kc2 = 0; kc2 < 4; ++kc2) {
            uint32_t a0[4], a1[4];
            ldm4(a0, Pb + kc2 * 64);
            ldm4(a1, Pb + kc2 * 64 + 32);
#pragma unroll
            for (int nt = 0; nt < 4; ++nt) {
                uint32_t b[4];
                ldm4(b, Wb + nt * 8 * PITCH + kc2 * 64);
                mma16816(acc[nt], a0[0], a0[1], a0[2], a0[3], b[0], b[1]);
                mma16816(acc[nt], a1[0], a1[1], a1[2], a1[3], b[2], b[3]);
            }
        }
    }

    // ---- epilogue: row sums + normalize + store ----
    ls += __shfl_xor_sync(0xffffffffu, ls, 1);
    ls += __shfl_xor_sync(0xffffffffu, ls, 2);
    ls += __shfl_xor_sync(0xffffffffu, ls, 4);
    float* sLS = (float*)(sm + OFF_LS);
    if ((l & 7) == 0) sLS[prow] = ls;
    __syncthreads();
    const float inv0 = 1.f / sLS[rg * 16 + (l >> 2)];
    const float inv1 = 1.f / sLS[rg * 16 + (l >> 2) + 8];
    const int r0 = i0 + rg * 16 + (l >> 2);
    const int cb = nc * 32 + (l & 3) * 2;
#pragma unroll
    for (int nt = 0; nt < 4; ++nt) {
        *(float2*)&out[(size_t)r0 * FD + cb + nt * 8] =
            make_float2(acc[nt][0] * inv0, acc[nt][1] * inv0);
        *(float2*)&out[(size_t)(r0 + 8) * FD + cb + nt * 8] =
            make_float2(acc[nt][2] * inv1, acc[nt][3] * inv1);
    }
}

// ---------------- launcher ---------------------------------------------------
extern "C" void kernel_launch(void* const* d_in, const int* in_sizes, int n_in,
                              void* d_out, int out_size) {
    const float* h   = (const float*)d_in[0];
    const int*   adj = (const int*)d_in[1];
    const float* W   = (const float*)d_in[2];
    const float* a   = (const float*)d_in[3];
    float* out = (float*)d_out;

    k_wh<<<NN / 64, 256>>>(h, W, a);
    k_max<<<1, 256>>>();
    k_pre<<<NN / 512, 512>>>();
    cudaFuncSetAttribute(k_flash, cudaFuncAttributeMaxDynamicSharedMemorySize, SMEMSZ);
    k_flash<<<NN / 64, 512, SMEMSZ>>>(adj, out);
}

// round 12
// speedup vs baseline: 1.5011x; 1.5011x over previous
#include <cuda_runtime.h>
#include <cuda_fp16.h>
#include <cstdint>

#define NN 8192
#define FD 128
#define ALPHA 0.2f

__device__ float  g_Wa1[FD], g_Wa2[FD];
__device__ float  g_es[NN], g_ed[NN], g_maxed;
__device__ float  g_A[NN], g_B[NN];
__device__ float2 g_jfg[NN];                 // {F, G}
__device__ __half g_W16T[FD * FD];           // [fo][k]
__device__ __half g_WhT[(size_t)FD * NN];    // [f][node]
__device__ float  g_part[2u * NN * FD];
__device__ float  g_lsp[2 * NN];

__device__ __forceinline__ float leakyf(float x) { return fmaxf(x, ALPHA * x); }
__device__ __forceinline__ uint32_t packh2(float x, float y) {
    __half2 h = __floats2half2_rn(x, y);
    return reinterpret_cast<uint32_t&>(h);
}
__device__ __forceinline__ void mma16816(float* c,
                                         uint32_t a0, uint32_t a1, uint32_t a2, uint32_t a3,
                                         uint32_t b0, uint32_t b1) {
    asm volatile(
        "mma.sync.aligned.m16n8k16.row.col.f32.f16.f16.f32 "
        "{%0,%1,%2,%3}, {%4,%5,%6,%7}, {%8,%9}, {%0,%1,%2,%3};\n"
        : "+f"(c[0]), "+f"(c[1]), "+f"(c[2]), "+f"(c[3])
        : "r"(a0), "r"(a1), "r"(a2), "r"(a3), "r"(b0), "r"(b1));
}
__device__ __forceinline__ void cp16(void* s, const void* g) {
    unsigned sa = (unsigned)__cvta_generic_to_shared(s);
    asm volatile("cp.async.cg.shared.global [%0], [%1], 16;\n" :: "r"(sa), "l"(g));
}
__device__ __forceinline__ void cp8(void* s, const void* g) {
    unsigned sa = (unsigned)__cvta_generic_to_shared(s);
    asm volatile("cp.async.ca.shared.global [%0], [%1], 8;\n" :: "r"(sa), "l"(g));
}
__device__ __forceinline__ void ldm4(uint32_t* r, uint32_t a) {
    asm volatile("ldmatrix.sync.aligned.m8n8.x4.shared.b16 {%0,%1,%2,%3}, [%4];"
                 : "=r"(r[0]), "=r"(r[1]), "=r"(r[2]), "=r"(r[3]) : "r"(a));
}

// ---- k_init: block0 computes Wa1/Wa2; blocks 1..64 transpose W to fp16 ------
__global__ void k_init(const float* __restrict__ W, const float* __restrict__ a) {
    if (blockIdx.x == 0) {
        int i = threadIdx.x;
        if (i < FD) {
            const float* wr = W + i * FD;
            float s1 = 0.f, s2 = 0.f;
#pragma unroll 8
            for (int j = 0; j < FD; ++j) {
                float w = wr[j];
                s1 += w * a[j];
                s2 += w * a[FD + j];
            }
            g_Wa1[i] = s1; g_Wa2[i] = s2;
        }
    } else {
        int n = (blockIdx.x - 1) * 256 + threadIdx.x;   // n = k*128 + fo
        int k = n >> 7, fo = n & 127;
        g_W16T[fo * FD + k] = __float2half(W[n]);
    }
}

// ---- k_esd: es/ed exact fp32 GEMV (warp per row) ----------------------------
__global__ void __launch_bounds__(256) k_esd(const float* __restrict__ h) {
    __shared__ float s1[FD], s2[FD];
    int t = threadIdx.x, l = t & 31, w = t >> 5;
    if (t < FD) { s1[t] = g_Wa1[t]; s2[t] = g_Wa2[t]; }
    __syncthreads();
    int i = blockIdx.x * 8 + w;
    float4 hv0 = *(const float4*)(h + (size_t)i * FD + l * 4);
    float e1 = hv0.x*s1[l*4] + hv0.y*s1[l*4+1] + hv0.z*s1[l*4+2] + hv0.w*s1[l*4+3];
    float e2 = hv0.x*s2[l*4] + hv0.y*s2[l*4+1] + hv0.z*s2[l*4+2] + hv0.w*s2[l*4+3];
#pragma unroll
    for (int o = 16; o; o >>= 1) {
        e1 += __shfl_xor_sync(0xffffffffu, e1, o);
        e2 += __shfl_xor_sync(0xffffffffu, e2, o);
    }
    if (l == 0) { g_es[i] = e1; g_ed[i] = e2; }
}

__global__ void k_max() {
    __shared__ float red[256];
    int t = threadIdx.x;
    float m = -1e30f;
    for (int i = t; i < NN; i += 256) m = fmaxf(m, g_ed[i]);
    red[t] = m;
    __syncthreads();
#pragma unroll
    for (int s = 128; s; s >>= 1) {
        if (t < s) red[t] = fmaxf(red[t], red[t + s]);
        __syncthreads();
    }
    if (t == 0) g_maxed = red[0];
}
__global__ void k_pre() {
    int i = blockIdx.x * 512 + threadIdx.x;
    float mx = g_maxed;
    float es = g_es[i], ed = g_ed[i];
    float m = leakyf(es + mx);
    g_A[i] = __expf(es + mx - m);
    g_B[i] = __expf(0.2f * (es + mx) - m);
    g_jfg[i] = make_float2(__expf(ed - mx), __expf(0.2f * (ed - mx)));
}

// ---- k_wh16: WhT = (h@W)^T in fp16 via HMMA ---------------------------------
#define PITCH 272
__global__ void __launch_bounds__(256) k_wh16(const float* __restrict__ h) {
    __shared__ __align__(16) char sb[128 * PITCH + 64 * PITCH];
    char* sA = sb;                       // 64 x 272 (fp16 rows of h)
    char* sB = sb + 64 * PITCH;          // 128 x 272 (W16T)
    const uint32_t smu = (uint32_t)__cvta_generic_to_shared(sb);
    const int t = threadIdx.x, l = t & 31, w = t >> 5;
    const int i0 = blockIdx.x * 64;
#pragma unroll
    for (int m = 0; m < 8; ++m) {        // h tile -> fp16
        int idx = t + m * 256, r = idx >> 5, c4 = idx & 31;
        float4 v = *(const float4*)(h + (size_t)(i0 + r) * FD + c4 * 4);
        uint2 pk; pk.x = packh2(v.x, v.y); pk.y = packh2(v.z, v.w);
        *(uint2*)(sA + r * PITCH + c4 * 8) = pk;
    }
#pragma unroll
    for (int m = 0; m < 8; ++m) {        // W16T tile
        int idx = t + m * 256, r = idx >> 4, c8 = idx & 15;
        cp16(sB + r * PITCH + c8 * 16, g_W16T + r * FD + c8 * 8);
    }
    asm volatile("cp.async.commit_group;\ncp.async.wait_group 0;\n");
    __syncthreads();

    const int rg = w >> 2, nc = w & 3;   // 2 x 4 warps, 32x32 tiles
    float acc[2][4][4];
#pragma unroll
    for (int a = 0; a < 2; ++a)
#pragma unroll
        for (int n = 0; n < 4; ++n)
#pragma unroll
            for (int i = 0; i < 4; ++i) acc[a][n][i] = 0.f;
    uint32_t Pb0 = smu + (rg * 32 + (l & 15)) * PITCH + (l >> 4) * 16;
    uint32_t Pb1 = Pb0 + 16 * PITCH;
    uint32_t Wb  = smu + 64 * PITCH + (nc * 32 + (l & 7)) * PITCH + (l >> 3) * 16;
#pragma unroll
    for (int kc2 = 0; kc2 < 4; ++kc2) {
        uint32_t a0[4], a1[4], a2[4], a3[4];
        ldm4(a0, Pb0 + kc2 * 64); ldm4(a1, Pb0 + kc2 * 64 + 32);
        ldm4(a2, Pb1 + kc2 * 64); ldm4(a3, Pb1 + kc2 * 64 + 32);
#pragma unroll
        for (int nt = 0; nt < 4; ++nt) {
            uint32_t b[4];
            ldm4(b, Wb + nt * 8 * PITCH + kc2 * 64);
            mma16816(acc[0][nt], a0[0], a0[1], a0[2], a0[3], b[0], b[1]);
            mma16816(acc[0][nt], a1[0], a1[1], a1[2], a1[3], b[2], b[3]);
            mma16816(acc[1][nt], a2[0], a2[1], a2[2], a2[3], b[0], b[1]);
            mma16816(acc[1][nt], a3[0], a3[1], a3[2], a3[3], b[2], b[3]);
        }
    }
    __syncthreads();
    float (*T)[132] = reinterpret_cast<float(*)[132]>(sb);
#pragma unroll
    for (int a = 0; a < 2; ++a)
#pragma unroll
        for (int nt = 0; nt < 4; ++nt) {
            int row = rg * 32 + a * 16 + (l >> 2);
            int col = nc * 32 + nt * 8 + (l & 3) * 2;
            *(float2*)&T[row][col]     = make_float2(acc[a][nt][0], acc[a][nt][1]);
            *(float2*)&T[row + 8][col] = make_float2(acc[a][nt][2], acc[a][nt][3]);
        }
    __syncthreads();
    {
        int c = t >> 1, hf = t & 1;
#pragma unroll
        for (int g = 0; g < 2; ++g) {
            uint4 pk;
            int r0 = hf * 32 + g * 16;
            pk.x = packh2(T[r0+0][c],  T[r0+1][c]);
            pk.y = packh2(T[r0+2][c],  T[r0+3][c]);
            pk.z = packh2(T[r0+4][c],  T[r0+5][c]);
            pk.w = packh2(T[r0+6][c],  T[r0+7][c]);
            uint4 pk2;
            pk2.x = packh2(T[r0+8][c],  T[r0+9][c]);
            pk2.y = packh2(T[r0+10][c], T[r0+11][c]);
            pk2.z = packh2(T[r0+12][c], T[r0+13][c]);
            pk2.w = packh2(T[r0+14][c], T[r0+15][c]);
            *(uint4*)(g_WhT + (size_t)c * NN + i0 + r0)     = pk;
            *(uint4*)(g_WhT + (size_t)c * NN + i0 + r0 + 8) = pk2;
        }
    }
}

// ---- k_flash: 128 CTAs = 64 i-blocks x 2 j-halves; 512 thr ------------------
#define OFF_P  0
#define OFF_W0 34816
#define OFF_W1 69632
#define OFF_J0 104448
#define OFF_J1 105984
#define SMEMSZ 107520

__global__ void __launch_bounds__(512) k_flash(const int* __restrict__ adj) {
    extern __shared__ __align__(16) char sm[];
    const uint32_t smu = (uint32_t)__cvta_generic_to_shared(sm);
    const int t = threadIdx.x, l = t & 31, w = t >> 5;
    const int ib = blockIdx.x >> 1, jhalf = blockIdx.x & 1;
    const int i0 = ib * 128, jbase = jhalf * 4096;
    const int cg = l;                  // 4 j-cols per thread
    const int rb = w * 8;              // 8 rows per thread

    float Ar[8], Br[8], lsr[8];
#pragma unroll
    for (int r = 0; r < 8; ++r) {
        Ar[r] = g_A[i0 + rb + r];
        Br[r] = g_B[i0 + rb + r];
        lsr[r] = 0.f;
    }

    const int rg = w >> 2, nc = w & 3;
    const uint32_t Pb0 = smu + OFF_P + (rg * 32 + (l & 15)) * PITCH + (l >> 4) * 16;
    const uint32_t Pb1 = Pb0 + 16 * PITCH;
    const uint32_t Wcol = (uint32_t)((nc * 32 + (l & 7)) * PITCH + (l >> 3) * 16);
    float acc[2][4][4];
#pragma unroll
    for (int a = 0; a < 2; ++a)
#pragma unroll
        for (int n = 0; n < 4; ++n)
#pragma unroll
            for (int i = 0; i < 4; ++i) acc[a][n][i] = 0.f;

    auto issue = [&](int buf, int jb) {
        const int j0 = jbase + jb * 128;
        char* Wt = sm + (buf ? OFF_W1 : OFF_W0);
        char* J  = sm + (buf ? OFF_J1 : OFF_J0);
#pragma unroll
        for (int mm = 0; mm < 4; ++mm) {
            int idx = t + mm * 512, f = idx >> 4, c8 = idx & 15;
            cp16(Wt + f * PITCH + c8 * 16, g_WhT + (size_t)f * NN + j0 + c8 * 8);
        }
        if (t < 128) cp8(J + (t >> 2) * 48 + (t & 3) * 8, g_jfg + j0 + t);
    };

    issue(0, 0);
    asm volatile("cp.async.commit_group;\n");
    int4 areg[8];
#pragma unroll
    for (int r = 0; r < 8; ++r)
        areg[r] = *(const int4*)(adj + (size_t)(i0 + rb + r) * NN + jbase + cg * 4);

    for (int jb = 0; jb < 32; ++jb) {
        const int buf = jb & 1;
        __syncthreads();
        if (jb + 1 < 32) issue(buf ^ 1, jb + 1);
        asm volatile("cp.async.commit_group;\n");
        asm volatile("cp.async.wait_group 1;\n");
        __syncthreads();

        // P phase
        const char* J = sm + (buf ? OFF_J1 : OFF_J0);
        float4 j01 = *(const float4*)(J + cg * 48);        // F0 G0 F1 G1
        float4 j23 = *(const float4*)(J + cg * 48 + 16);   // F2 G2 F3 G3
        char* Pp = sm + OFF_P + rb * PITCH + cg * 8;
#pragma unroll
        for (int r = 0; r < 8; ++r) {
            int4 q = areg[r];
            float p0 = fmaxf(Ar[r] * j01.x, Br[r] * j01.y); p0 = q.x ? p0 : 0.f;
            float p1 = fmaxf(Ar[r] * j01.z, Br[r] * j01.w); p1 = q.y ? p1 : 0.f;
            float p2 = fmaxf(Ar[r] * j23.x, Br[r] * j23.y); p2 = q.z ? p2 : 0.f;
            float p3 = fmaxf(Ar[r] * j23.z, Br[r] * j23.w); p3 = q.w ? p3 : 0.f;
            lsr[r] += (p0 + p1) + (p2 + p3);
            uint2 pk; pk.x = packh2(p0, p1); pk.y = packh2(p2, p3);
            *(uint2*)(Pp + r * PITCH) = pk;
        }
        if (jb + 1 < 32) {
#pragma unroll
            for (int r = 0; r < 8; ++r)
                areg[r] = *(const int4*)(adj + (size_t)(i0 + rb + r) * NN + jbase +
                                         (jb + 1) * 128 + cg * 4);
        }
        __syncthreads();

        // MMA phase
        const uint32_t Wb = smu + (buf ? OFF_W1 : OFF_W0) + Wcol;
#pragma unroll
        for (int kc2 = 0; kc2 < 4; ++kc2) {
            uint32_t a0[4], a1[4], a2[4], a3[4];
            ldm4(a0, Pb0 + kc2 * 64); ldm4(a1, Pb0 + kc2 * 64 + 32);
            ldm4(a2, Pb1 + kc2 * 64); ldm4(a3, Pb1 + kc2 * 64 + 32);
#pragma unroll
            for (int nt = 0; nt < 4; ++nt) {
                uint32_t b[4];
                ldm4(b, Wb + nt * 8 * PITCH + kc2 * 64);
                mma16816(acc[0][nt], a0[0], a0[1], a0[2], a0[3], b[0], b[1]);
                mma16816(acc[0][nt], a1[0], a1[1], a1[2], a1[3], b[2], b[3]);
                mma16816(acc[1][nt], a2[0], a2[1], a2[2], a2[3], b[0], b[1]);
                mma16816(acc[1][nt], a3[0], a3[1], a3[2], a3[3], b[2], b[3]);
            }
        }
    }

    // row sums
#pragma unroll
    for (int r = 0; r < 8; ++r) {
        float v = lsr[r];
#pragma unroll
        for (int o = 16; o; o >>= 1) v += __shfl_xor_sync(0xffffffffu, v, o);
        if (l == r) g_lsp[jhalf * NN + i0 + rb + r] = v;
    }
    // partial numerator
#pragma unroll
    for (int a = 0; a < 2; ++a)
#pragma unroll
        for (int nt = 0; nt < 4; ++nt) {
            int row = i0 + rg * 32 + a * 16 + (l >> 2);
            int col = nc * 32 + nt * 8 + (l & 3) * 2;
            *(float2*)&g_part[((size_t)jhalf * NN + row) * FD + col] =
                make_float2(acc[a][nt][0], acc[a][nt][1]);
            *(float2*)&g_part[((size_t)jhalf * NN + row + 8) * FD + col] =
                make_float2(acc[a][nt][2], acc[a][nt][3]);
        }
}

// ---- k_comb -----------------------------------------------------------------
__global__ void k_comb(float* __restrict__ out) {
    int idx = blockIdx.x * 512 + threadIdx.x;
    int i = idx >> 7;
    float num = g_part[idx] + g_part[(size_t)NN * FD + idx];
    float den = g_lsp[i] + g_lsp[NN + i];
    out[idx] = num / den;
}

// ---- launcher ---------------------------------------------------------------
extern "C" void kernel_launch(void* const* d_in, const int* in_sizes, int n_in,
                              void* d_out, int out_size) {
    const float* h   = (const float*)d_in[0];
    const int*   adj = (const int*)d_in[1];
    const float* W   = (const float*)d_in[2];
    const float* a   = (const float*)d_in[3];
    float* out = (float*)d_out;

    k_init<<<65, 256>>>(W, a);
    k_wh16<<<NN / 64, 256>>>(h);
    k_esd<<<NN / 8, 256>>>(h);
    k_max<<<1, 256>>>();
    k_pre<<<NN / 512, 512>>>();
    cudaFuncSetAttribute(k_flash, cudaFuncAttributeMaxDynamicSharedMemorySize, SMEMSZ);
    k_flash<<<128, 512, SMEMSZ>>>(adj);
    k_comb<<<NN * FD / 512, 512>>>(out);
}

// round 13
// speedup vs baseline: 1.6413x; 1.0934x over previous
#include <cuda_runtime.h>
#include <cuda_fp16.h>
#include <cstdint>

#define NN 8192
#define FD 128
#define ALPHA 0.2f

__device__ float  g_Wa1[FD], g_Wa2[FD];
__device__ float  g_es[NN], g_ed[NN];
__device__ unsigned g_maxu;
__device__ float  g_A[NN], g_B[NN];
__device__ float2 g_jfg[NN];                 // {F, G}
__device__ __half g_W16T[FD * FD];           // [fo][k]
__device__ __half g_WhT[(size_t)FD * NN];    // [f][node]
__device__ float  g_part[2u * NN * FD];
__device__ float  g_lsp[2 * NN];

__device__ __forceinline__ float leakyf(float x) { return fmaxf(x, ALPHA * x); }
__device__ __forceinline__ uint32_t packh2(float x, float y) {
    __half2 h = __floats2half2_rn(x, y);
    return reinterpret_cast<uint32_t&>(h);
}
__device__ __forceinline__ void mma16816(float* c,
                                         uint32_t a0, uint32_t a1, uint32_t a2, uint32_t a3,
                                         uint32_t b0, uint32_t b1) {
    asm volatile(
        "mma.sync.aligned.m16n8k16.row.col.f32.f16.f16.f32 "
        "{%0,%1,%2,%3}, {%4,%5,%6,%7}, {%8,%9}, {%0,%1,%2,%3};\n"
        : "+f"(c[0]), "+f"(c[1]), "+f"(c[2]), "+f"(c[3])
        : "r"(a0), "r"(a1), "r"(a2), "r"(a3), "r"(b0), "r"(b1));
}
__device__ __forceinline__ void cp16(void* s, const void* g) {
    unsigned sa = (unsigned)__cvta_generic_to_shared(s);
    asm volatile("cp.async.cg.shared.global [%0], [%1], 16;\n" :: "r"(sa), "l"(g));
}
__device__ __forceinline__ void ldm4(uint32_t* r, uint32_t a) {
    asm volatile("ldmatrix.sync.aligned.m8n8.x4.shared.b16 {%0,%1,%2,%3}, [%4];"
                 : "=r"(r[0]), "=r"(r[1]), "=r"(r[2]), "=r"(r[3]) : "r"(a));
}
__device__ __forceinline__ unsigned fenc(float f) {
    unsigned b = __float_as_uint(f);
    return (b & 0x80000000u) ? ~b : (b | 0x80000000u);
}
__device__ __forceinline__ float fdec(unsigned k) {
    unsigned b = (k & 0x80000000u) ? (k & 0x7FFFFFFFu) : ~k;
    return __uint_as_float(b);
}

// ---- k_init: Wa1/Wa2, W fp16 transpose, reset max ---------------------------
__global__ void k_init(const float* __restrict__ W, const float* __restrict__ a) {
    if (blockIdx.x == 0) {
        int i = threadIdx.x;
        if (i == 0) g_maxu = 0u;
        if (i < FD) {
            const float* wr = W + i * FD;
            float s1 = 0.f, s2 = 0.f;
#pragma unroll 8
            for (int j = 0; j < FD; ++j) {
                float w = wr[j];
                s1 += w * a[j];
                s2 += w * a[FD + j];
            }
            g_Wa1[i] = s1; g_Wa2[i] = s2;
        }
    } else {
        int n = (blockIdx.x - 1) * 256 + threadIdx.x;
        int k = n >> 7, fo = n & 127;
        g_W16T[fo * FD + k] = __float2half(W[n]);
    }
}

// ---- k_esd: es/ed exact fp32 GEMV + fused global max ------------------------
__global__ void __launch_bounds__(256) k_esd(const float* __restrict__ h) {
    __shared__ float s1[FD], s2[FD];
    int t = threadIdx.x, l = t & 31, w = t >> 5;
    if (t < FD) { s1[t] = g_Wa1[t]; s2[t] = g_Wa2[t]; }
    __syncthreads();
    int i = blockIdx.x * 8 + w;
    float4 hv0 = *(const float4*)(h + (size_t)i * FD + l * 4);
    float e1 = hv0.x*s1[l*4] + hv0.y*s1[l*4+1] + hv0.z*s1[l*4+2] + hv0.w*s1[l*4+3];
    float e2 = hv0.x*s2[l*4] + hv0.y*s2[l*4+1] + hv0.z*s2[l*4+2] + hv0.w*s2[l*4+3];
#pragma unroll
    for (int o = 16; o; o >>= 1) {
        e1 += __shfl_xor_sync(0xffffffffu, e1, o);
        e2 += __shfl_xor_sync(0xffffffffu, e2, o);
    }
    if (l == 0) {
        g_es[i] = e1; g_ed[i] = e2;
        atomicMax(&g_maxu, fenc(e2));
    }
}

__global__ void k_pre() {
    int i = blockIdx.x * 512 + threadIdx.x;
    float mx = fdec(g_maxu);
    float es = g_es[i], ed = g_ed[i];
    float m = leakyf(es + mx);
    g_A[i] = __expf(es + mx - m);
    g_B[i] = __expf(0.2f * (es + mx) - m);
    g_jfg[i] = make_float2(__expf(ed - mx), __expf(0.2f * (ed - mx)));
}

// ---- k_wh16: WhT = (h@W)^T in fp16 via HMMA ---------------------------------
#define PITCH 272
__global__ void __launch_bounds__(256) k_wh16(const float* __restrict__ h) {
    __shared__ __align__(16) char sb[128 * PITCH + 64 * PITCH];
    char* sA = sb;
    char* sB = sb + 64 * PITCH;
    const uint32_t smu = (uint32_t)__cvta_generic_to_shared(sb);
    const int t = threadIdx.x, l = t & 31, w = t >> 5;
    const int i0 = blockIdx.x * 64;
#pragma unroll
    for (int m = 0; m < 8; ++m) {
        int idx = t + m * 256, r = idx >> 5, c4 = idx & 31;
        float4 v = *(const float4*)(h + (size_t)(i0 + r) * FD + c4 * 4);
        uint2 pk; pk.x = packh2(v.x, v.y); pk.y = packh2(v.z, v.w);
        *(uint2*)(sA + r * PITCH + c4 * 8) = pk;
    }
#pragma unroll
    for (int m = 0; m < 8; ++m) {
        int idx = t + m * 256, r = idx >> 4, c8 = idx & 15;
        cp16(sB + r * PITCH + c8 * 16, g_W16T + r * FD + c8 * 8);
    }
    asm volatile("cp.async.commit_group;\ncp.async.wait_group 0;\n");
    __syncthreads();

    const int rg = w >> 2, nc = w & 3;
    float acc[2][4][4];
#pragma unroll
    for (int a = 0; a < 2; ++a)
#pragma unroll
        for (int n = 0; n < 4; ++n)
#pragma unroll
            for (int i = 0; i < 4; ++i) acc[a][n][i] = 0.f;
    uint32_t Pb0 = smu + (rg * 32 + (l & 15)) * PITCH + (l >> 4) * 16;
    uint32_t Pb1 = Pb0 + 16 * PITCH;
    uint32_t Wb  = smu + 64 * PITCH + (nc * 32 + (l & 7)) * PITCH + (l >> 3) * 16;
#pragma unroll
    for (int kc2 = 0; kc2 < 4; ++kc2) {
        uint32_t a0[4], a1[4], a2[4], a3[4];
        ldm4(a0, Pb0 + kc2 * 64); ldm4(a1, Pb0 + kc2 * 64 + 32);
        ldm4(a2, Pb1 + kc2 * 64); ldm4(a3, Pb1 + kc2 * 64 + 32);
#pragma unroll
        for (int nt = 0; nt < 4; ++nt) {
            uint32_t b[4];
            ldm4(b, Wb + nt * 8 * PITCH + kc2 * 64);
            mma16816(acc[0][nt], a0[0], a0[1], a0[2], a0[3], b[0], b[1]);
            mma16816(acc[0][nt], a1[0], a1[1], a1[2], a1[3], b[2], b[3]);
            mma16816(acc[1][nt], a2[0], a2[1], a2[2], a2[3], b[0], b[1]);
            mma16816(acc[1][nt], a3[0], a3[1], a3[2], a3[3], b[2], b[3]);
        }
    }
    __syncthreads();
    float (*T)[132] = reinterpret_cast<float(*)[132]>(sb);
#pragma unroll
    for (int a = 0; a < 2; ++a)
#pragma unroll
        for (int nt = 0; nt < 4; ++nt) {
            int row = rg * 32 + a * 16 + (l >> 2);
            int col = nc * 32 + nt * 8 + (l & 3) * 2;
            *(float2*)&T[row][col]     = make_float2(acc[a][nt][0], acc[a][nt][1]);
            *(float2*)&T[row + 8][col] = make_float2(acc[a][nt][2], acc[a][nt][3]);
        }
    __syncthreads();
    {
        int c = t >> 1, hf = t & 1;
#pragma unroll
        for (int g = 0; g < 2; ++g) {
            int r0 = hf * 32 + g * 16;
            uint4 pk, pk2;
            pk.x  = packh2(T[r0+0][c],  T[r0+1][c]);
            pk.y  = packh2(T[r0+2][c],  T[r0+3][c]);
            pk.z  = packh2(T[r0+4][c],  T[r0+5][c]);
            pk.w  = packh2(T[r0+6][c],  T[r0+7][c]);
            pk2.x = packh2(T[r0+8][c],  T[r0+9][c]);
            pk2.y = packh2(T[r0+10][c], T[r0+11][c]);
            pk2.z = packh2(T[r0+12][c], T[r0+13][c]);
            pk2.w = packh2(T[r0+14][c], T[r0+15][c]);
            *(uint4*)(g_WhT + (size_t)c * NN + i0 + r0)     = pk;
            *(uint4*)(g_WhT + (size_t)c * NN + i0 + r0 + 8) = pk2;
        }
    }
}

// ---- k_flash: pipelined single-sync loop ------------------------------------
#define OFF_P0 0
#define OFF_P1 34816
#define OFF_W0 69632
#define OFF_W1 104448
#define OFF_AB 139264
#define SMEMSZ 140288

__global__ void __launch_bounds__(512) k_flash(const int* __restrict__ adj) {
    extern __shared__ __align__(16) char sm[];
    const uint32_t smu = (uint32_t)__cvta_generic_to_shared(sm);
    const int t = threadIdx.x, l = t & 31, w = t >> 5;
    const int ib = blockIdx.x >> 1, jhalf = blockIdx.x & 1;
    const int i0 = ib * 128, jbase = jhalf * 4096;
    const int cg = l;                  // 4 j-cols per thread
    const int rb = w * 8;              // 8 rows per thread
    float* sAB = (float*)(sm + OFF_AB);

    if (t < 128) { sAB[t] = g_A[i0 + t]; sAB[128 + t] = g_B[i0 + t]; }

    const int rg = w >> 2, nc = w & 3;
    const uint32_t Wcol = (uint32_t)((nc * 32 + (l & 7)) * PITCH + (l >> 3) * 16);
    const uint32_t Prow = (uint32_t)((rg * 32 + (l & 15)) * PITCH + (l >> 4) * 16);
    float acc[2][4][4];
#pragma unroll
    for (int a = 0; a < 2; ++a)
#pragma unroll
        for (int n = 0; n < 4; ++n)
#pragma unroll
            for (int i = 0; i < 4; ++i) acc[a][n][i] = 0.f;
    float lsr[8];
#pragma unroll
    for (int r = 0; r < 8; ++r) lsr[r] = 0.f;

    auto issueW = [&](int buf, int jb) {
        const int j0 = jbase + jb * 128;
        char* Wt = sm + (buf ? OFF_W1 : OFF_W0);
#pragma unroll
        for (int mm = 0; mm < 4; ++mm) {
            int idx = t + mm * 512, f = idx >> 4, c8 = idx & 15;
            cp16(Wt + f * PITCH + c8 * 16, g_WhT + (size_t)f * NN + j0 + c8 * 8);
        }
    };

    issueW(0, 0);
    asm volatile("cp.async.commit_group;\n");

    int4 areg[8];
    float4 jA, jB;
    {
        const float4* jp = (const float4*)(g_jfg + jbase + cg * 4);
        jA = jp[0]; jB = jp[1];
#pragma unroll
        for (int r = 0; r < 8; ++r)
            areg[r] = *(const int4*)(adj + (size_t)(i0 + rb + r) * NN + jbase + cg * 4);
    }
    __syncthreads();   // sAB visible

    // P(0)
    {
        char* Pp = sm + OFF_P0 + rb * PITCH + cg * 8;
#pragma unroll
        for (int r = 0; r < 8; ++r) {
            int4 q = areg[r];
            float Af = sAB[rb + r], Bf = sAB[128 + rb + r];
            float p0 = fmaxf(Af * jA.x, Bf * jA.y); p0 = q.x ? p0 : 0.f;
            float p1 = fmaxf(Af * jA.z, Bf * jA.w); p1 = q.y ? p1 : 0.f;
            float p2 = fmaxf(Af * jB.x, Bf * jB.y); p2 = q.z ? p2 : 0.f;
            float p3 = fmaxf(Af * jB.z, Bf * jB.w); p3 = q.w ? p3 : 0.f;
            lsr[r] += (p0 + p1) + (p2 + p3);
            uint2 pk; pk.x = packh2(p0, p1); pk.y = packh2(p2, p3);
            *(uint2*)(Pp + r * PITCH) = pk;
        }
        const float4* jp = (const float4*)(g_jfg + jbase + 128 + cg * 4);
        jA = jp[0]; jB = jp[1];
#pragma unroll
        for (int r = 0; r < 8; ++r)
            areg[r] = *(const int4*)(adj + (size_t)(i0 + rb + r) * NN + jbase + 128 + cg * 4);
    }

    for (int jb = 0; jb < 32; ++jb) {
        const int buf = jb & 1;
        asm volatile("cp.async.wait_group 0;\n");
        __syncthreads();          // P(jb) + W(jb) visible; prev reads done
        if (jb + 1 < 32) {
            issueW(buf ^ 1, jb + 1);
            asm volatile("cp.async.commit_group;\n");
        }

        // P(jb+1) into P[buf^1]
        if (jb + 1 < 32) {
            char* Pp = sm + (buf ? OFF_P0 : OFF_P1) + rb * PITCH + cg * 8;
#pragma unroll
            for (int r = 0; r < 8; ++r) {
                int4 q = areg[r];
                float Af = sAB[rb + r], Bf = sAB[128 + rb + r];
                float p0 = fmaxf(Af * jA.x, Bf * jA.y); p0 = q.x ? p0 : 0.f;
                float p1 = fmaxf(Af * jA.z, Bf * jA.w); p1 = q.y ? p1 : 0.f;
                float p2 = fmaxf(Af * jB.x, Bf * jB.y); p2 = q.z ? p2 : 0.f;
                float p3 = fmaxf(Af * jB.z, Bf * jB.w); p3 = q.w ? p3 : 0.f;
                lsr[r] += (p0 + p1) + (p2 + p3);
                uint2 pk; pk.x = packh2(p0, p1); pk.y = packh2(p2, p3);
                *(uint2*)(Pp + r * PITCH) = pk;
            }
            if (jb + 2 < 32) {
                const int joff = jbase + (jb + 2) * 128;
                const float4* jp = (const float4*)(g_jfg + joff + cg * 4);
                jA = jp[0]; jB = jp[1];
#pragma unroll
                for (int r = 0; r < 8; ++r)
                    areg[r] = *(const int4*)(adj + (size_t)(i0 + rb + r) * NN + joff + cg * 4);
            }
        }

        // MMA(jb) on P[buf], W[buf]
        const uint32_t Pb0 = smu + (buf ? OFF_P1 : OFF_P0) + Prow;
        const uint32_t Pb1 = Pb0 + 16 * PITCH;
        const uint32_t Wb  = smu + (buf ? OFF_W1 : OFF_W0) + Wcol;
#pragma unroll
        for (int kc2 = 0; kc2 < 4; ++kc2) {
            uint32_t a0[4], a1[4], a2[4], a3[4];
            ldm4(a0, Pb0 + kc2 * 64); ldm4(a1, Pb0 + kc2 * 64 + 32);
            ldm4(a2, Pb1 + kc2 * 64); ldm4(a3, Pb1 + kc2 * 64 + 32);
#pragma unroll
            for (int nt = 0; nt < 4; ++nt) {
                uint32_t b[4];
                ldm4(b, Wb + nt * 8 * PITCH + kc2 * 64);
                mma16816(acc[0][nt], a0[0], a0[1], a0[2], a0[3], b[0], b[1]);
                mma16816(acc[0][nt], a1[0], a1[1], a1[2], a1[3], b[2], b[3]);
                mma16816(acc[1][nt], a2[0], a2[1], a2[2], a2[3], b[0], b[1]);
                mma16816(acc[1][nt], a3[0], a3[1], a3[2], a3[3], b[2], b[3]);
            }
        }
    }

    // row sums
#pragma unroll
    for (int r = 0; r < 8; ++r) {
        float v = lsr[r];
#pragma unroll
        for (int o = 16; o; o >>= 1) v += __shfl_xor_sync(0xffffffffu, v, o);
        if (l == r) g_lsp[jhalf * NN + i0 + rb + r] = v;
    }
    // partial numerator
#pragma unroll
    for (int a = 0; a < 2; ++a)
#pragma unroll
        for (int nt = 0; nt < 4; ++nt) {
            int row = i0 + rg * 32 + a * 16 + (l >> 2);
            int col = nc * 32 + nt * 8 + (l & 3) * 2;
            *(float2*)&g_part[((size_t)jhalf * NN + row) * FD + col] =
                make_float2(acc[a][nt][0], acc[a][nt][1]);
            *(float2*)&g_part[((size_t)jhalf * NN + row + 8) * FD + col] =
                make_float2(acc[a][nt][2], acc[a][nt][3]);
        }
}

// ---- k_comb -----------------------------------------------------------------
__global__ void k_comb(float* __restrict__ out) {
    int idx = blockIdx.x * 512 + threadIdx.x;
    int i = idx >> 7;
    float num = g_part[idx] + g_part[(size_t)NN * FD + idx];
    float den = g_lsp[i] + g_lsp[NN + i];
    out[idx] = num / den;
}

// ---- launcher ---------------------------------------------------------------
extern "C" void kernel_launch(void* const* d_in, const int* in_sizes, int n_in,
                              void* d_out, int out_size) {
    const float* h   = (const float*)d_in[0];
    const int*   adj = (const int*)d_in[1];
    const float* W   = (const float*)d_in[2];
    const float* a   = (const float*)d_in[3];
    float* out = (float*)d_out;

    k_init<<<65, 256>>>(W, a);
    k_wh16<<<NN / 64, 256>>>(h);
    k_esd<<<NN / 8, 256>>>(h);
    k_pre<<<NN / 512, 512>>>();
    cudaFuncSetAttribute(k_flash, cudaFuncAttributeMaxDynamicSharedMemorySize, SMEMSZ);
    k_flash<<<128, 512, SMEMSZ>>>(adj);
    k_comb<<<NN * FD / 512, 512>>>(out);
}

// round 14
// speedup vs baseline: 2.0717x; 1.2623x over previous
#include <cuda_runtime.h>
#include <cuda_fp16.h>
#include <cstdint>

#define NN 8192
#define FD 128
#define ALPHA 0.2f

__device__ float  g_Wa1[FD], g_Wa2[FD];
__device__ float  g_es[NN], g_ed[NN];
__device__ unsigned g_maxu;
__device__ float  g_A[NN], g_B[NN];
__device__ float2 g_jfg[NN];                 // {F, G}
__device__ __half g_W16T[FD * FD];           // [fo][k]
__device__ __half g_WhT[(size_t)FD * NN];    // [f][node]
__device__ float  g_part[2u * NN * FD];
__device__ float  g_lsp[2 * NN];

__device__ __forceinline__ float leakyf(float x) { return fmaxf(x, ALPHA * x); }
__device__ __forceinline__ uint32_t packh2(float x, float y) {
    __half2 h = __floats2half2_rn(x, y);
    return reinterpret_cast<uint32_t&>(h);
}
__device__ __forceinline__ void mma16816(float* c,
                                         uint32_t a0, uint32_t a1, uint32_t a2, uint32_t a3,
                                         uint32_t b0, uint32_t b1) {
    asm volatile(
        "mma.sync.aligned.m16n8k16.row.col.f32.f16.f16.f32 "
        "{%0,%1,%2,%3}, {%4,%5,%6,%7}, {%8,%9}, {%0,%1,%2,%3};\n"
        : "+f"(c[0]), "+f"(c[1]), "+f"(c[2]), "+f"(c[3])
        : "r"(a0), "r"(a1), "r"(a2), "r"(a3), "r"(b0), "r"(b1));
}
__device__ __forceinline__ void cp16(void* s, const void* g) {
    unsigned sa = (unsigned)__cvta_generic_to_shared(s);
    asm volatile("cp.async.cg.shared.global [%0], [%1], 16;\n" :: "r"(sa), "l"(g));
}
__device__ __forceinline__ void ldm4(uint32_t* r, uint32_t a) {
    asm volatile("ldmatrix.sync.aligned.m8n8.x4.shared.b16 {%0,%1,%2,%3}, [%4];"
                 : "=r"(r[0]), "=r"(r[1]), "=r"(r[2]), "=r"(r[3]) : "r"(a));
}
__device__ __forceinline__ unsigned fenc(float f) {
    unsigned b = __float_as_uint(f);
    return (b & 0x80000000u) ? ~b : (b | 0x80000000u);
}
__device__ __forceinline__ float fdec(unsigned k) {
    unsigned b = (k & 0x80000000u) ? (k & 0x7FFFFFFFu) : ~k;
    return __uint_as_float(b);
}

// ---- k_init: Wa1/Wa2, W fp16 transpose, reset max ---------------------------
__global__ void k_init(const float* __restrict__ W, const float* __restrict__ a) {
    if (blockIdx.x == 0) {
        int i = threadIdx.x;
        if (i == 0) g_maxu = 0u;
        if (i < FD) {
            const float* wr = W + i * FD;
            float s1 = 0.f, s2 = 0.f;
#pragma unroll 8
            for (int j = 0; j < FD; ++j) {
                float w = wr[j];
                s1 += w * a[j];
                s2 += w * a[FD + j];
            }
            g_Wa1[i] = s1; g_Wa2[i] = s2;
        }
    } else {
        int n = (blockIdx.x - 1) * 256 + threadIdx.x;
        int k = n >> 7, fo = n & 127;
        g_W16T[fo * FD + k] = __float2half(W[n]);
    }
}

// ---- k_esd: es/ed exact fp32 GEMV + fused global max ------------------------
__global__ void __launch_bounds__(256) k_esd(const float* __restrict__ h) {
    __shared__ float s1[FD], s2[FD];
    int t = threadIdx.x, l = t & 31, w = t >> 5;
    if (t < FD) { s1[t] = g_Wa1[t]; s2[t] = g_Wa2[t]; }
    __syncthreads();
    int i = blockIdx.x * 8 + w;
    float4 hv0 = *(const float4*)(h + (size_t)i * FD + l * 4);
    float e1 = hv0.x*s1[l*4] + hv0.y*s1[l*4+1] + hv0.z*s1[l*4+2] + hv0.w*s1[l*4+3];
    float e2 = hv0.x*s2[l*4] + hv0.y*s2[l*4+1] + hv0.z*s2[l*4+2] + hv0.w*s2[l*4+3];
#pragma unroll
    for (int o = 16; o; o >>= 1) {
        e1 += __shfl_xor_sync(0xffffffffu, e1, o);
        e2 += __shfl_xor_sync(0xffffffffu, e2, o);
    }
    if (l == 0) {
        g_es[i] = e1; g_ed[i] = e2;
        atomicMax(&g_maxu, fenc(e2));
    }
}

// ---- k_wh16: fused pre + WhT = (h@W)^T in fp16 via HMMA ---------------------
#define PITCH 272
__global__ void __launch_bounds__(256) k_wh16(const float* __restrict__ h) {
    __shared__ __align__(16) char sb[128 * PITCH + 64 * PITCH];
    char* sA = sb;
    char* sB = sb + 64 * PITCH;
    const uint32_t smu = (uint32_t)__cvta_generic_to_shared(sb);
    const int t = threadIdx.x, l = t & 31, w = t >> 5;
    const int i0 = blockIdx.x * 64;

    // fused k_pre: rows/cols i0..i0+63
    if (t < 64) {
        int i = i0 + t;
        float mx = fdec(g_maxu);
        float es = g_es[i], ed = g_ed[i];
        float m = leakyf(es + mx);
        g_A[i] = __expf(es + mx - m);
        g_B[i] = __expf(0.2f * (es + mx) - m);
        g_jfg[i] = make_float2(__expf(ed - mx), __expf(0.2f * (ed - mx)));
    }

#pragma unroll
    for (int m = 0; m < 8; ++m) {
        int idx = t + m * 256, r = idx >> 5, c4 = idx & 31;
        float4 v = *(const float4*)(h + (size_t)(i0 + r) * FD + c4 * 4);
        uint2 pk; pk.x = packh2(v.x, v.y); pk.y = packh2(v.z, v.w);
        *(uint2*)(sA + r * PITCH + c4 * 8) = pk;
    }
#pragma unroll
    for (int m = 0; m < 8; ++m) {
        int idx = t + m * 256, r = idx >> 4, c8 = idx & 15;
        cp16(sB + r * PITCH + c8 * 16, g_W16T + r * FD + c8 * 8);
    }
    asm volatile("cp.async.commit_group;\ncp.async.wait_group 0;\n");
    __syncthreads();

    const int rg = w >> 2, nc = w & 3;
    float acc[2][4][4];
#pragma unroll
    for (int a = 0; a < 2; ++a)
#pragma unroll
        for (int n = 0; n < 4; ++n)
#pragma unroll
            for (int i = 0; i < 4; ++i) acc[a][n][i] = 0.f;
    uint32_t Pb0 = smu + (rg * 32 + (l & 15)) * PITCH + (l >> 4) * 16;
    uint32_t Pb1 = Pb0 + 16 * PITCH;
    uint32_t Wb  = smu + 64 * PITCH + (nc * 32 + (l & 7)) * PITCH + (l >> 3) * 16;
#pragma unroll
    for (int kc2 = 0; kc2 < 4; ++kc2) {
        uint32_t a0[4], a1[4], a2[4], a3[4];
        ldm4(a0, Pb0 + kc2 * 64); ldm4(a1, Pb0 + kc2 * 64 + 32);
        ldm4(a2, Pb1 + kc2 * 64); ldm4(a3, Pb1 + kc2 * 64 + 32);
#pragma unroll
        for (int nt = 0; nt < 4; ++nt) {
            uint32_t b[4];
            ldm4(b, Wb + nt * 8 * PITCH + kc2 * 64);
            mma16816(acc[0][nt], a0[0], a0[1], a0[2], a0[3], b[0], b[1]);
            mma16816(acc[0][nt], a1[0], a1[1], a1[2], a1[3], b[2], b[3]);
            mma16816(acc[1][nt], a2[0], a2[1], a2[2], a2[3], b[0], b[1]);
            mma16816(acc[1][nt], a3[0], a3[1], a3[2], a3[3], b[2], b[3]);
        }
    }
    __syncthreads();
    float (*T)[132] = reinterpret_cast<float(*)[132]>(sb);
#pragma unroll
    for (int a = 0; a < 2; ++a)
#pragma unroll
        for (int nt = 0; nt < 4; ++nt) {
            int row = rg * 32 + a * 16 + (l >> 2);
            int col = nc * 32 + nt * 8 + (l & 3) * 2;
            *(float2*)&T[row][col]     = make_float2(acc[a][nt][0], acc[a][nt][1]);
            *(float2*)&T[row + 8][col] = make_float2(acc[a][nt][2], acc[a][nt][3]);
        }
    __syncthreads();
    {
        int c = t >> 1, hf = t & 1;
#pragma unroll
        for (int g = 0; g < 2; ++g) {
            int r0 = hf * 32 + g * 16;
            uint4 pk, pk2;
            pk.x  = packh2(T[r0+0][c],  T[r0+1][c]);
            pk.y  = packh2(T[r0+2][c],  T[r0+3][c]);
            pk.z  = packh2(T[r0+4][c],  T[r0+5][c]);
            pk.w  = packh2(T[r0+6][c],  T[r0+7][c]);
            pk2.x = packh2(T[r0+8][c],  T[r0+9][c]);
            pk2.y = packh2(T[r0+10][c], T[r0+11][c]);
            pk2.z = packh2(T[r0+12][c], T[r0+13][c]);
            pk2.w = packh2(T[r0+14][c], T[r0+15][c]);
            *(uint4*)(g_WhT + (size_t)c * NN + i0 + r0)     = pk;
            *(uint4*)(g_WhT + (size_t)c * NN + i0 + r0 + 8) = pk2;
        }
    }
}

// ---- k_flash: pipelined, phase-staggered ------------------------------------
#define OFF_P0 0
#define OFF_P1 34816
#define OFF_W0 69632
#define OFF_W1 104448
#define OFF_AB 139264
#define SMEMSZ 140288

__global__ void __launch_bounds__(512) k_flash(const int* __restrict__ adj) {
    extern __shared__ __align__(16) char sm[];
    const uint32_t smu = (uint32_t)__cvta_generic_to_shared(sm);
    const int t = threadIdx.x, l = t & 31, w = t >> 5;
    const int ib = blockIdx.x >> 1, jhalf = blockIdx.x & 1;
    const int i0 = ib * 128, jbase = jhalf * 4096;
    const int cg = l;
    const int rb = w * 8;
    float* sAB = (float*)(sm + OFF_AB);

    if (t < 128) { sAB[t] = g_A[i0 + t]; sAB[128 + t] = g_B[i0 + t]; }

    const int rg = w >> 2, nc = w & 3;
    const uint32_t Wcol = (uint32_t)((nc * 32 + (l & 7)) * PITCH + (l >> 3) * 16);
    const uint32_t Prow = (uint32_t)((rg * 32 + (l & 15)) * PITCH + (l >> 4) * 16);
    float acc[2][4][4];
#pragma unroll
    for (int a = 0; a < 2; ++a)
#pragma unroll
        for (int n = 0; n < 4; ++n)
#pragma unroll
            for (int i = 0; i < 4; ++i) acc[a][n][i] = 0.f;
    float lsr[8];
#pragma unroll
    for (int r = 0; r < 8; ++r) lsr[r] = 0.f;

    auto issueW = [&](int buf, int jb) {
        const int j0 = jbase + jb * 128;
        char* Wt = sm + (buf ? OFF_W1 : OFF_W0);
#pragma unroll
        for (int mm = 0; mm < 4; ++mm) {
            int idx = t + mm * 512, f = idx >> 4, c8 = idx & 15;
            cp16(Wt + f * PITCH + c8 * 16, g_WhT + (size_t)f * NN + j0 + c8 * 8);
        }
    };

    issueW(0, 0);
    asm volatile("cp.async.commit_group;\n");

    int4 areg[8];
    float4 jA, jB;
    {
        const float4* jp = (const float4*)(g_jfg + jbase + cg * 4);
        jA = jp[0]; jB = jp[1];
#pragma unroll
        for (int r = 0; r < 8; ++r)
            areg[r] = *(const int4*)(adj + (size_t)(i0 + rb + r) * NN + jbase + cg * 4);
    }
    __syncthreads();

    // P(0)
    {
        char* Pp = sm + OFF_P0 + rb * PITCH + cg * 8;
#pragma unroll
        for (int r = 0; r < 8; ++r) {
            int4 q = areg[r];
            float Af = sAB[rb + r], Bf = sAB[128 + rb + r];
            float p0 = fmaxf(Af * jA.x, Bf * jA.y); p0 = q.x ? p0 : 0.f;
            float p1 = fmaxf(Af * jA.z, Bf * jA.w); p1 = q.y ? p1 : 0.f;
            float p2 = fmaxf(Af * jB.x, Bf * jB.y); p2 = q.z ? p2 : 0.f;
            float p3 = fmaxf(Af * jB.z, Bf * jB.w); p3 = q.w ? p3 : 0.f;
            lsr[r] += (p0 + p1) + (p2 + p3);
            uint2 pk; pk.x = packh2(p0, p1); pk.y = packh2(p2, p3);
            *(uint2*)(Pp + r * PITCH) = pk;
        }
        const float4* jp = (const float4*)(g_jfg + jbase + 128 + cg * 4);
        jA = jp[0]; jB = jp[1];
#pragma unroll
        for (int r = 0; r < 8; ++r)
            areg[r] = *(const int4*)(adj + (size_t)(i0 + rb + r) * NN + jbase + 128 + cg * 4);
    }

    for (int jb = 0; jb < 32; ++jb) {
        const int buf = jb & 1;
        asm volatile("cp.async.wait_group 0;\n");
        __syncthreads();
        if (jb + 1 < 32) {
            issueW(buf ^ 1, jb + 1);
            asm volatile("cp.async.commit_group;\n");
        }

        auto doP = [&]() {
            if (jb + 1 >= 32) return;
            char* Pp = sm + (buf ? OFF_P0 : OFF_P1) + rb * PITCH + cg * 8;
#pragma unroll
            for (int r = 0; r < 8; ++r) {
                int4 q = areg[r];
                float Af = sAB[rb + r], Bf = sAB[128 + rb + r];
                float p0 = fmaxf(Af * jA.x, Bf * jA.y); p0 = q.x ? p0 : 0.f;
                float p1 = fmaxf(Af * jA.z, Bf * jA.w); p1 = q.y ? p1 : 0.f;
                float p2 = fmaxf(Af * jB.x, Bf * jB.y); p2 = q.z ? p2 : 0.f;
                float p3 = fmaxf(Af * jB.z, Bf * jB.w); p3 = q.w ? p3 : 0.f;
                lsr[r] += (p0 + p1) + (p2 + p3);
                uint2 pk; pk.x = packh2(p0, p1); pk.y = packh2(p2, p3);
                *(uint2*)(Pp + r * PITCH) = pk;
            }
            if (jb + 2 < 32) {
                const int joff = jbase + (jb + 2) * 128;
                const float4* jp = (const float4*)(g_jfg + joff + cg * 4);
                jA = jp[0]; jB = jp[1];
#pragma unroll
                for (int r = 0; r < 8; ++r)
                    areg[r] = *(const int4*)(adj + (size_t)(i0 + rb + r) * NN + joff + cg * 4);
            }
        };
        auto doMMA = [&]() {
            const uint32_t Pb0 = smu + (buf ? OFF_P1 : OFF_P0) + Prow;
            const uint32_t Pb1 = Pb0 + 16 * PITCH;
            const uint32_t Wb  = smu + (buf ? OFF_W1 : OFF_W0) + Wcol;
#pragma unroll
            for (int kc2 = 0; kc2 < 4; ++kc2) {
                uint32_t a0[4], a1[4], a2[4], a3[4];
                ldm4(a0, Pb0 + kc2 * 64); ldm4(a1, Pb0 + kc2 * 64 + 32);
                ldm4(a2, Pb1 + kc2 * 64); ldm4(a3, Pb1 + kc2 * 64 + 32);
#pragma unroll
                for (int nt = 0; nt < 4; ++nt) {
                    uint32_t b[4];
                    ldm4(b, Wb + nt * 8 * PITCH + kc2 * 64);
                    mma16816(acc[0][nt], a0[0], a0[1], a0[2], a0[3], b[0], b[1]);
                    mma16816(acc[0][nt], a1[0], a1[1], a1[2], a1[3], b[2], b[3]);
                    mma16816(acc[1][nt], a2[0], a2[1], a2[2], a2[3], b[0], b[1]);
                    mma16816(acc[1][nt], a3[0], a3[1], a3[2], a3[3], b[2], b[3]);
                }
            }
        };

        if (w & 1) { doMMA(); doP(); }
        else       { doP(); doMMA(); }
    }

    // row sums
#pragma unroll
    for (int r = 0; r < 8; ++r) {
        float v = lsr[r];
#pragma unroll
        for (int o = 16; o; o >>= 1) v += __shfl_xor_sync(0xffffffffu, v, o);
        if (l == r) g_lsp[jhalf * NN + i0 + rb + r] = v;
    }
    // partial numerator
#pragma unroll
    for (int a = 0; a < 2; ++a)
#pragma unroll
        for (int nt = 0; nt < 4; ++nt) {
            int row = i0 + rg * 32 + a * 16 + (l >> 2);
            int col = nc * 32 + nt * 8 + (l & 3) * 2;
            *(float2*)&g_part[((size_t)jhalf * NN + row) * FD + col] =
                make_float2(acc[a][nt][0], acc[a][nt][1]);
            *(float2*)&g_part[((size_t)jhalf * NN + row + 8) * FD + col] =
                make_float2(acc[a][nt][2], acc[a][nt][3]);
        }
}

// ---- k_comb -----------------------------------------------------------------
__global__ void k_comb(float* __restrict__ out) {
    int idx = blockIdx.x * 512 + threadIdx.x;
    int i = idx >> 7;
    float num = g_part[idx] + g_part[(size_t)NN * FD + idx];
    float den = g_lsp[i] + g_lsp[NN + i];
    out[idx] = num / den;
}

// ---- launcher ---------------------------------------------------------------
extern "C" void kernel_launch(void* const* d_in, const int* in_sizes, int n_in,
                              void* d_out, int out_size) {
    const float* h   = (const float*)d_in[0];
    const int*   adj = (const int*)d_in[1];
    const float* W   = (const float*)d_in[2];
    const float* a   = (const float*)d_in[3];
    float* out = (float*)d_out;

    k_init<<<65, 256>>>(W, a);
    k_esd<<<NN / 8, 256>>>(h);
    k_wh16<<<NN / 64, 256>>>(h);
    cudaFuncSetAttribute(k_flash, cudaFuncAttributeMaxDynamicSharedMemorySize, SMEMSZ);
    k_flash<<<128, 512, SMEMSZ>>>(adj);
    k_comb<<<NN * FD / 512, 512>>>(out);
}